// round 2
// baseline (speedup 1.0000x reference)
#include <cuda_runtime.h>
#include <cstdint>

// Problem constants
#define B_     64
#define T_     16
#define IMG_   84
#define P_     7
#define GH_    12
#define GW_    12
#define NS_    144      // GH*GW
#define GD_    8        // T/TUBE
#define TUBE_  2
#define K_     98       // TUBE * P*P
#define E_     1024
#define NTOK_  1152     // GD*NS
#define M_     73728    // B * NTOK

// Scratch (device globals; allocation is forbidden)
__device__ float g_tub[(size_t)K_ * M_];   // [k][m]  28.9 MB
__device__ float g_Wt[(size_t)K_ * E_];    // [k][e]

// ---------------------------------------------------------------------------
// packed f32x2 helpers (ptxas will not auto-fuse FFMA2; must come from PTX)
// ---------------------------------------------------------------------------
__device__ __forceinline__ unsigned long long pack2(float x, float y) {
    unsigned long long r;
    asm("mov.b64 %0, {%1, %2};" : "=l"(r) : "f"(x), "f"(y));
    return r;
}
__device__ __forceinline__ void fma2(unsigned long long& acc,
                                     unsigned long long a,
                                     unsigned long long b) {
    asm("fma.rn.f32x2 %0, %1, %2, %0;" : "+l"(acc) : "l"(a), "l"(b));
}
__device__ __forceinline__ float2 unpack2(unsigned long long v) {
    float2 r;
    asm("mov.b64 {%0, %1}, %2;" : "=f"(r.x), "=f"(r.y) : "l"(v));
    return r;
}

// ---------------------------------------------------------------------------
// 1) Gather: video [B,T,1,84,84] -> g_tub [K][M]   (K-major so GEMM loads coalesce)
//    block = one (b,t) frame. token m = b*1152 + (t/2)*144 + s, k = (t%2)*49 + pi*7+pj
// ---------------------------------------------------------------------------
__global__ void gather_kernel(const float* __restrict__ video) {
    __shared__ float frame[IMG_ * IMG_];       // 28224 B
    int bt = blockIdx.x;
    int b  = bt >> 4;
    int t  = bt & 15;
    const float* src = video + (size_t)bt * (IMG_ * IMG_);
    for (int i = threadIdx.x; i < IMG_ * IMG_; i += blockDim.x)
        frame[i] = src[i];
    __syncthreads();

    int d = t >> 1, ts = t & 1;
    int mbase = b * NTOK_ + d * NS_;
    int kbase = ts * 49;

    for (int i = threadIdx.x; i < 49 * NS_; i += blockDim.x) {
        int k  = i / NS_;
        int s  = i - k * NS_;
        int pi = k / P_, pj = k - pi * P_;
        int h  = s / GW_, w = s - h * GW_;
        float v = frame[(h * P_ + pi) * IMG_ + (w * P_ + pj)];
        g_tub[(size_t)(kbase + k) * M_ + mbase + s] = v;   // 576B-contig runs per k
    }
}

// ---------------------------------------------------------------------------
// 2) Transpose W [E][K] -> g_Wt [K][E]
// ---------------------------------------------------------------------------
__global__ void wt_kernel(const float* __restrict__ W) {
    __shared__ float tile[32][33];
    int e0 = blockIdx.x * 32;
    int k0 = blockIdx.y * 32;
    int tx = threadIdx.x, ty = threadIdx.y;

    int k = k0 + tx;                       // coalesced read along K
    if (k < K_) tile[ty][tx] = W[(size_t)(e0 + ty) * K_ + k];
    __syncthreads();
    int ko = k0 + ty, eo = e0 + tx;        // coalesced write along E
    if (ko < K_) g_Wt[(size_t)ko * E_ + eo] = tile[tx][ty];
}

// ---------------------------------------------------------------------------
// 3) GEMM: out[m][e] = sum_k g_tub[k][m]*g_Wt[k][e] + bias[e] + pos[m%1152][e]
//    128x128 CTA tile, 8x8 per thread, fma.rn.f32x2 mainloop
// ---------------------------------------------------------------------------
#define MT 128
#define ET 128
#define KC 32

__global__ __launch_bounds__(256, 2)
void gemm_kernel(const float* __restrict__ bias,
                 const float* __restrict__ pos,
                 float* __restrict__ out) {
    __shared__ float sT[KC][MT];   // 16 KB
    __shared__ float sW[KC][ET];   // 16 KB

    int tid = threadIdx.x;
    int tx = tid & 15;             // embed group
    int ty = tid >> 4;             // token group
    int m0 = blockIdx.x * MT;
    int e0 = blockIdx.y * ET;

    unsigned long long acc[8][4];
#pragma unroll
    for (int i = 0; i < 8; ++i)
#pragma unroll
        for (int j = 0; j < 4; ++j) acc[i][j] = 0ull;

#pragma unroll 1
    for (int c = 0; c < 4; ++c) {
        int kc0 = c * KC;
        __syncthreads();
        // stage 32 K-rows of both operands (float4, fully coalesced, zero-pad K>=98)
#pragma unroll
        for (int r = 0; r < 4; ++r) {
            int li = tid + r * 256;        // 0..1023 float4 slots
            int kr = li >> 5;              // 0..31
            int c4 = li & 31;              // 0..31
            int k  = kc0 + kr;
            float4 vT = make_float4(0.f, 0.f, 0.f, 0.f);
            float4 vW = vT;
            if (k < K_) {
                vT = *(const float4*)(g_tub + (size_t)k * M_ + m0 + c4 * 4);
                vW = *(const float4*)(g_Wt  + (size_t)k * E_ + e0 + c4 * 4);
            }
            *(float4*)&sT[kr][c4 * 4] = vT;
            *(float4*)&sW[kr][c4 * 4] = vW;
        }
        __syncthreads();

#define STEP(kk)                                                           \
        {                                                                  \
            float4 a0 = *(const float4*)&sT[(kk)][ty * 8];                 \
            float4 a1 = *(const float4*)&sT[(kk)][ty * 8 + 4];             \
            ulonglong2 b01 = *(const ulonglong2*)&sW[(kk)][tx * 8];        \
            ulonglong2 b23 = *(const ulonglong2*)&sW[(kk)][tx * 8 + 4];    \
            unsigned long long bb0 = b01.x, bb1 = b01.y;                   \
            unsigned long long bb2 = b23.x, bb3 = b23.y;                   \
            float av[8] = {a0.x, a0.y, a0.z, a0.w, a1.x, a1.y, a1.z, a1.w};\
            _Pragma("unroll")                                              \
            for (int i = 0; i < 8; ++i) {                                  \
                unsigned long long ad = pack2(av[i], av[i]);               \
                fma2(acc[i][0], ad, bb0);                                  \
                fma2(acc[i][1], ad, bb1);                                  \
                fma2(acc[i][2], ad, bb2);                                  \
                fma2(acc[i][3], ad, bb3);                                  \
            }                                                              \
        }

        if (c < 3) {
#pragma unroll
            for (int k = 0; k < KC; ++k) { STEP(k) }
        } else {
            // tail: only k = 96, 97 are real
#pragma unroll
            for (int k = 0; k < 2; ++k) { STEP(k) }
        }
#undef STEP
    }

    // epilogue: + bias + pos_embed, float4 stores
    float4 bia0 = *(const float4*)(bias + e0 + tx * 8);
    float4 bia1 = *(const float4*)(bias + e0 + tx * 8 + 4);

#pragma unroll
    for (int i = 0; i < 8; ++i) {
        int m = m0 + ty * 8 + i;
        int n = m % NTOK_;
        const float* pp = pos + (size_t)n * E_ + e0 + tx * 8;
        float4 p0 = *(const float4*)pp;
        float4 p1 = *(const float4*)(pp + 4);
        float2 v0 = unpack2(acc[i][0]);
        float2 v1 = unpack2(acc[i][1]);
        float2 v2 = unpack2(acc[i][2]);
        float2 v3 = unpack2(acc[i][3]);
        float4 o0 = make_float4(v0.x + bia0.x + p0.x, v0.y + bia0.y + p0.y,
                                v1.x + bia0.z + p0.z, v1.y + bia0.w + p0.w);
        float4 o1 = make_float4(v2.x + bia1.x + p1.x, v2.y + bia1.y + p1.y,
                                v3.x + bia1.z + p1.z, v3.y + bia1.w + p1.w);
        float* op = out + (size_t)m * E_ + e0 + tx * 8;
        *(float4*)op       = o0;
        *(float4*)(op + 4) = o1;
    }
}

// ---------------------------------------------------------------------------
extern "C" void kernel_launch(void* const* d_in, const int* in_sizes, int n_in,
                              void* d_out, int out_size) {
    const float* video = (const float*)d_in[0];   // [64,16,1,84,84]
    const float* W     = (const float*)d_in[1];   // [1024,98]
    const float* bias  = (const float*)d_in[2];   // [1024]
    const float* pos   = (const float*)d_in[3];   // [1,1152,1024]
    float* out         = (float*)d_out;           // [64,1152,1024]

    gather_kernel<<<B_ * T_, 256>>>(video);
    wt_kernel<<<dim3(E_ / 32, (K_ + 31) / 32), dim3(32, 32)>>>(W);
    gemm_kernel<<<dim3(M_ / MT, E_ / ET), 256>>>(bias, pos, out);
}

// round 3
// speedup vs baseline: 1.7607x; 1.7607x over previous
#include <cuda_runtime.h>
#include <cstdint>

// Problem constants
#define B_     64
#define T_     16
#define IMG_   84
#define P_     7
#define GH_    12
#define GW_    12
#define NS_    144      // GH*GW
#define GD_    8        // T/TUBE
#define TUBE_  2
#define K_     98       // TUBE * P*P
#define KP_    104      // K padded to multiple of 8 (pad rows stay zero)
#define E_     1024
#define NTOK_  1152     // GD*NS
#define M_     73728    // B * NTOK

// Scratch (device globals; allocation is forbidden). Zero-initialized at module
// load; rows k in [98,104) are never written -> permanent zero padding.
__device__ float g_tub[(size_t)KP_ * M_];   // [k][m]  ~30.7 MB
__device__ float g_Wt[(size_t)KP_ * E_];    // [k][e]

// ---------------------------------------------------------------------------
// tf32 helpers
// ---------------------------------------------------------------------------
__device__ __forceinline__ float to_tf32(float f) {
    uint32_t u;
    asm("cvt.rna.tf32.f32 %0, %1;" : "=r"(u) : "f"(f));
    return __uint_as_float(u);
}

__device__ __forceinline__ void mma_tf32(float4& d, const uint32_t a[4],
                                         const uint32_t b[2]) {
    asm("mma.sync.aligned.m16n8k8.row.col.f32.tf32.tf32.f32 "
        "{%0,%1,%2,%3}, {%4,%5,%6,%7}, {%8,%9}, {%0,%1,%2,%3};"
        : "+f"(d.x), "+f"(d.y), "+f"(d.z), "+f"(d.w)
        : "r"(a[0]), "r"(a[1]), "r"(a[2]), "r"(a[3]), "r"(b[0]), "r"(b[1]));
}

// ---------------------------------------------------------------------------
// 1) Gather: video [B,T,1,84,84] -> g_tub [K][M] (tf32-rounded, K-major)
// ---------------------------------------------------------------------------
__global__ void gather_kernel(const float* __restrict__ video) {
    __shared__ float frame[IMG_ * IMG_];
    int bt = blockIdx.x;
    int b  = bt >> 4;
    int t  = bt & 15;
    const float* src = video + (size_t)bt * (IMG_ * IMG_);
    for (int i = threadIdx.x; i < IMG_ * IMG_; i += blockDim.x)
        frame[i] = src[i];
    __syncthreads();

    int d = t >> 1, ts = t & 1;
    int mbase = b * NTOK_ + d * NS_;
    int kbase = ts * 49;

    for (int i = threadIdx.x; i < 49 * NS_; i += blockDim.x) {
        int k  = i / NS_;
        int s  = i - k * NS_;
        int pi = k / P_, pj = k - pi * P_;
        int h  = s / GW_, w = s - h * GW_;
        float v = frame[(h * P_ + pi) * IMG_ + (w * P_ + pj)];
        g_tub[(size_t)(kbase + k) * M_ + mbase + s] = to_tf32(v);
    }
}

// ---------------------------------------------------------------------------
// 2) Transpose W [E][K] -> g_Wt [K][E] (tf32-rounded)
// ---------------------------------------------------------------------------
__global__ void wt_kernel(const float* __restrict__ W) {
    __shared__ float tile[32][33];
    int e0 = blockIdx.x * 32;
    int k0 = blockIdx.y * 32;
    int tx = threadIdx.x, ty = threadIdx.y;

    int k = k0 + tx;
    if (k < K_) tile[ty][tx] = W[(size_t)(e0 + ty) * K_ + k];
    __syncthreads();
    int ko = k0 + ty, eo = e0 + tx;
    if (ko < K_) g_Wt[(size_t)ko * E_ + eo] = to_tf32(tile[tx][ty]);
}

// ---------------------------------------------------------------------------
// 3) GEMM (tf32 tensor cores): out[m][e] = sum_k A[k][m]*B[k][e] + bias + pos
//    CTA 128x128, 8 warps of 64x32, K-chunks of 8 (13 chunks over KP=104).
// ---------------------------------------------------------------------------
#define MT   128
#define ET   128
#define KC   8
#define NCH  (KP_ / KC)     // 13
#define SP   136            // padded smem row (floats): conflict-free frags

__global__ __launch_bounds__(256, 2)
void gemm_kernel(const float* __restrict__ bias,
                 const float* __restrict__ pos,
                 float* __restrict__ out) {
    __shared__ float sA[KC][SP];   // [k][m] 4.25 KB
    __shared__ float sB[KC][SP];   // [k][e]

    const int tid  = threadIdx.x;
    const int lane = tid & 31;
    const int w    = tid >> 5;     // 0..7
    const int wm   = w >> 2;       // 0..1  -> m offset wm*64
    const int wn   = w & 3;        // 0..3  -> n offset wn*32
    const int grp  = lane >> 2;    // 0..7
    const int tg   = lane & 3;     // 0..3

    const int e0 = blockIdx.x * ET;
    const int m0 = blockIdx.y * MT;

    // staging coords: each thread owns one float4 of A and one of B per chunk
    const int ks = tid >> 5;       // k row within chunk (0..7)
    const int qs = tid & 31;       // float4 index along m/e (0..31)

    const float* gA = g_tub + (size_t)ks * M_ + m0 + qs * 4;
    const float* gB = g_Wt  + (size_t)ks * E_ + e0 + qs * 4;

    float4 acc[4][4];
#pragma unroll
    for (int i = 0; i < 4; ++i)
#pragma unroll
        for (int j = 0; j < 4; ++j) acc[i][j] = make_float4(0.f, 0.f, 0.f, 0.f);

    // prologue: stage chunk 0
    {
        float4 va = *(const float4*)gA;
        float4 vb = *(const float4*)gB;
        *(float4*)&sA[ks][qs * 4] = va;
        *(float4*)&sB[ks][qs * 4] = vb;
    }
    __syncthreads();

#pragma unroll 1
    for (int c = 0; c < NCH; ++c) {
        float4 na, nb;
        if (c < NCH - 1) {   // prefetch next chunk (hidden under MMAs)
            na = *(const float4*)(gA + (size_t)(c + 1) * KC * M_);
            nb = *(const float4*)(gB + (size_t)(c + 1) * KC * E_);
        }

        // load fragments (conflict-free thanks to SP=136 padding)
        uint32_t af[4][4], bf[4][2];
#pragma unroll
        for (int mf = 0; mf < 4; ++mf) {
            int r0 = wm * 64 + mf * 16 + grp;
            af[mf][0] = __float_as_uint(sA[tg][r0]);
            af[mf][1] = __float_as_uint(sA[tg][r0 + 8]);
            af[mf][2] = __float_as_uint(sA[tg + 4][r0]);
            af[mf][3] = __float_as_uint(sA[tg + 4][r0 + 8]);
        }
#pragma unroll
        for (int nf = 0; nf < 4; ++nf) {
            int cn = wn * 32 + nf * 8 + grp;
            bf[nf][0] = __float_as_uint(sB[tg][cn]);
            bf[nf][1] = __float_as_uint(sB[tg + 4][cn]);
        }

#pragma unroll
        for (int mf = 0; mf < 4; ++mf)
#pragma unroll
            for (int nf = 0; nf < 4; ++nf)
                mma_tf32(acc[mf][nf], af[mf], bf[nf]);

        __syncthreads();
        if (c < NCH - 1) {
            *(float4*)&sA[ks][qs * 4] = na;
            *(float4*)&sB[ks][qs * 4] = nb;
        }
        __syncthreads();
    }

    // epilogue: out = acc + bias + pos  (tiles never cross a batch boundary
    // since NTOK=1152 is a multiple of MT=128)
    const int ntile = m0 % NTOK_;
#pragma unroll
    for (int mf = 0; mf < 4; ++mf) {
        int mloc = wm * 64 + mf * 16 + grp;
        int r  = m0 + mloc;
        int n  = ntile + mloc;        // pos row for r
#pragma unroll
        for (int nf = 0; nf < 4; ++nf) {
            int col = e0 + wn * 32 + nf * 8 + 2 * tg;
            float2 bb = *(const float2*)(bias + col);
            float2 p0 = *(const float2*)(pos + (size_t)n * E_ + col);
            float2 p1 = *(const float2*)(pos + (size_t)(n + 8) * E_ + col);
            float4 a = acc[mf][nf];
            float2 o0 = make_float2(a.x + bb.x + p0.x, a.y + bb.y + p0.y);
            float2 o1 = make_float2(a.z + bb.x + p1.x, a.w + bb.y + p1.y);
            *(float2*)(out + (size_t)r * E_ + col)       = o0;
            *(float2*)(out + (size_t)(r + 8) * E_ + col) = o1;
        }
    }
}

// ---------------------------------------------------------------------------
extern "C" void kernel_launch(void* const* d_in, const int* in_sizes, int n_in,
                              void* d_out, int out_size) {
    const float* video = (const float*)d_in[0];   // [64,16,1,84,84]
    const float* W     = (const float*)d_in[1];   // [1024,98]
    const float* bias  = (const float*)d_in[2];   // [1024]
    const float* pos   = (const float*)d_in[3];   // [1,1152,1024]
    float* out         = (float*)d_out;           // [64,1152,1024]

    gather_kernel<<<B_ * T_, 256>>>(video);
    wt_kernel<<<dim3(E_ / 32, (K_ + 31) / 32), dim3(32, 32)>>>(W);
    gemm_kernel<<<dim3(E_ / ET, M_ / MT), 256>>>(bias, pos, out);
}

// round 5
// speedup vs baseline: 1.7998x; 1.0222x over previous
#include <cuda_runtime.h>
#include <cstdint>

// ---------------------------------------------------------------- constants
#define B_     64
#define T_     16
#define IMG_   84
#define P_     7
#define NS_    144
#define K_     98
#define KP_    112          // K padded to 7 chunks of 16 (pad rows stay zero)
#define E_     1024
#define NTOK_  1152
#define M_     73728

// Scratch (device globals, zero-init; k in [98,112) never written -> zero pad)
__device__ float g_tub[(size_t)KP_ * M_];   // [k][m]  33 MB (tf32-rounded)
__device__ float g_Wt[(size_t)KP_ * E_];    // [k][e]  (tf32-rounded)

// ---------------------------------------------------------------- helpers
__device__ __forceinline__ float to_tf32(float f) {
    uint32_t u;
    asm("cvt.rna.tf32.f32 %0, %1;" : "=r"(u) : "f"(f));
    return __uint_as_float(u);
}

__device__ __forceinline__ void mma_tf32(float4& d, const uint32_t a[4],
                                         const uint32_t b[2]) {
    asm("mma.sync.aligned.m16n8k8.row.col.f32.tf32.tf32.f32 "
        "{%0,%1,%2,%3}, {%4,%5,%6,%7}, {%8,%9}, {%0,%1,%2,%3};"
        : "+f"(d.x), "+f"(d.y), "+f"(d.z), "+f"(d.w)
        : "r"(a[0]), "r"(a[1]), "r"(a[2]), "r"(a[3]), "r"(b[0]), "r"(b[1]));
}

__device__ __forceinline__ uint32_t smem_u32(const void* p) {
    uint32_t a;
    asm("{ .reg .u64 t; cvta.to.shared.u64 t, %1; cvt.u32.u64 %0, t; }"
        : "=r"(a) : "l"(p));
    return a;
}
__device__ __forceinline__ void cpasync16(uint32_t dst, const void* src) {
    asm volatile("cp.async.cg.shared.global [%0], [%1], 16;"
                 :: "r"(dst), "l"(src));
}
#define CP_COMMIT() asm volatile("cp.async.commit_group;" ::: "memory")
#define CP_WAIT(n)  asm volatile("cp.async.wait_group %0;" :: "n"(n) : "memory")

// ---------------------------------------------------------------- prep
__global__ void gather_kernel(const float* __restrict__ video) {
    __shared__ float frame[IMG_ * IMG_];
    int bt = blockIdx.x, b = bt >> 4, t = bt & 15;
    const float* src = video + (size_t)bt * (IMG_ * IMG_);
    for (int i = threadIdx.x; i < IMG_ * IMG_; i += blockDim.x) frame[i] = src[i];
    __syncthreads();

    int d = t >> 1, ts = t & 1;
    int mbase = b * NTOK_ + d * NS_;
    int kbase = ts * 49;
    for (int i = threadIdx.x; i < 49 * NS_; i += blockDim.x) {
        int k  = i / NS_;
        int s  = i - k * NS_;
        int pi = k / P_, pj = k - pi * P_;
        int h  = s / 12, w = s - h * 12;
        float v = frame[(h * P_ + pi) * IMG_ + (w * P_ + pj)];
        g_tub[(size_t)(kbase + k) * M_ + mbase + s] = to_tf32(v);
    }
}

__global__ void wt_kernel(const float* __restrict__ W) {
    __shared__ float tile[32][33];
    int e0 = blockIdx.x * 32;
    int k0 = blockIdx.y * 32;
    int tx = threadIdx.x, ty = threadIdx.y;
    int k = k0 + tx;
    if (k < K_) tile[ty][tx] = W[(size_t)(e0 + ty) * K_ + k];
    __syncthreads();
    int ko = k0 + ty, eo = e0 + tx;
    if (ko < K_) g_Wt[(size_t)ko * E_ + eo] = to_tf32(tile[tx][ty]);
}

// ---------------------------------------------------------------- GEMM
// CTA tile 256(m) x 128(e); 8 warps, each 64x64. K chunks of 16 (7 chunks),
// cp.async 2-stage double buffer. tf32 m16n8k8 mma.sync.
#define MT   256
#define ET   128
#define KC   16
#define NCH  7
#define SAW  264            // sA row stride (floats), ≡8 mod 32 -> conflict-free
#define SBW  136            // sB row stride
#define SA_BUF (KC * SAW)   // floats per A buffer
#define SB_BUF (KC * SBW)
#define SMEM_BYTES ((2 * SA_BUF + 2 * SB_BUF) * 4)   // 51200 B

__global__ __launch_bounds__(256, 1)
void gemm_kernel(const float* __restrict__ bias,
                 const float* __restrict__ pos,
                 float* __restrict__ out) {
    extern __shared__ float sm[];
    float* sA = sm;                    // [2][KC][SAW]
    float* sB = sm + 2 * SA_BUF;       // [2][KC][SBW]
    const uint32_t sA_u = smem_u32(sA);
    const uint32_t sB_u = smem_u32(sB);

    const int tid  = threadIdx.x;
    const int lane = tid & 31;
    const int wid  = tid >> 5;
    const int grp  = lane >> 2;        // 0..7
    const int tg   = lane & 3;         // 0..3
    const int wm   = wid & 3;          // m-quadrant (0..3) -> wm*64
    const int wn   = wid >> 2;         // e-half (0..1)     -> wn*64

    const int e0 = blockIdx.x * ET;
    const int m0 = blockIdx.y * MT;

    // staging coords
    const int kA = tid >> 6;           // +r*4 rows   (A: 64 x16B per row)
    const int qA = tid & 63;
    const int kB = tid >> 5;           // +r*8 rows   (B: 32 x16B per row)
    const int qB = tid & 31;

    const float* gA = g_tub + (size_t)kA * M_ + m0 + qA * 4;
    const float* gB = g_Wt  + (size_t)kB * E_ + e0 + qB * 4;

    // stage one K-chunk `c` into buffer `buf`
    auto stage = [&](int c, int buf) {
        const float* a = gA + (size_t)c * KC * M_;
        uint32_t dA = sA_u + (buf * SA_BUF + kA * SAW + qA * 4) * 4;
#pragma unroll
        for (int r = 0; r < 4; ++r)
            cpasync16(dA + r * 4 * SAW * 4, a + (size_t)r * 4 * M_);
        const float* b = gB + (size_t)c * KC * E_;
        uint32_t dB = sB_u + (buf * SB_BUF + kB * SBW + qB * 4) * 4;
#pragma unroll
        for (int r = 0; r < 2; ++r)
            cpasync16(dB + r * 8 * SBW * 4, b + (size_t)r * 8 * E_);
        CP_COMMIT();
    };

    float4 acc[4][8];
#pragma unroll
    for (int i = 0; i < 4; ++i)
#pragma unroll
        for (int j = 0; j < 8; ++j) acc[i][j] = make_float4(0.f, 0.f, 0.f, 0.f);

    stage(0, 0);
    stage(1, 1);

#pragma unroll 1
    for (int c = 0; c < NCH; ++c) {
        if (c < NCH - 1) { CP_WAIT(1); } else { CP_WAIT(0); }
        __syncthreads();
        const int buf = c & 1;
        const float* bA = sA + buf * SA_BUF;
        const float* bB = sB + buf * SB_BUF;

        // load ALL fragments for this chunk (2 ksteps) into registers
        uint32_t af[2][4][4], bf[2][8][2];
#pragma unroll
        for (int ks = 0; ks < 2; ++ks) {
            const float* rowA0 = bA + (ks * 8 + tg) * SAW + wm * 64 + grp;
            const float* rowA1 = bA + (ks * 8 + tg + 4) * SAW + wm * 64 + grp;
#pragma unroll
            for (int mf = 0; mf < 4; ++mf) {
                af[ks][mf][0] = __float_as_uint(rowA0[mf * 16]);
                af[ks][mf][1] = __float_as_uint(rowA0[mf * 16 + 8]);
                af[ks][mf][2] = __float_as_uint(rowA1[mf * 16]);
                af[ks][mf][3] = __float_as_uint(rowA1[mf * 16 + 8]);
            }
            const float* rowB0 = bB + (ks * 8 + tg) * SBW + wn * 64 + grp;
            const float* rowB1 = bB + (ks * 8 + tg + 4) * SBW + wn * 64 + grp;
#pragma unroll
            for (int nf = 0; nf < 8; ++nf) {
                bf[ks][nf][0] = __float_as_uint(rowB0[nf * 8]);
                bf[ks][nf][1] = __float_as_uint(rowB1[nf * 8]);
            }
        }
        __syncthreads();                 // reads done -> buffer reusable
        if (c + 2 < NCH) stage(c + 2, buf);

#pragma unroll
        for (int ks = 0; ks < 2; ++ks)
#pragma unroll
            for (int mf = 0; mf < 4; ++mf)
#pragma unroll
                for (int nf = 0; nf < 8; ++nf)
                    mma_tf32(acc[mf][nf], af[ks][mf], bf[ks][nf]);
    }

    // ---- epilogue: out = acc + bias + pos (tile can cross batch boundary) ----
    const int n0 = m0 % NTOK_;
    float2 bb[8];
#pragma unroll
    for (int nf = 0; nf < 8; ++nf)
        bb[nf] = *(const float2*)(bias + e0 + wn * 64 + nf * 8 + tg * 2);

#pragma unroll
    for (int mf = 0; mf < 4; ++mf) {
        int rl = wm * 64 + mf * 16 + grp;
        int m  = m0 + rl;
        int n  = n0 + rl;        if (n  >= NTOK_) n  -= NTOK_;
        int n2 = n0 + rl + 8;    if (n2 >= NTOK_) n2 -= NTOK_;
        const float* pr0 = pos + (size_t)n  * E_ + e0 + wn * 64 + tg * 2;
        const float* pr1 = pos + (size_t)n2 * E_ + e0 + wn * 64 + tg * 2;
        float* or0 = out + (size_t)m * E_ + e0 + wn * 64 + tg * 2;
        float* or1 = or0 + 8 * E_;
#pragma unroll
        for (int nf = 0; nf < 8; ++nf) {
            float2 p0 = *(const float2*)(pr0 + nf * 8);
            float2 p1 = *(const float2*)(pr1 + nf * 8);
            float4 a  = acc[mf][nf];
            float2 o0 = make_float2(a.x + bb[nf].x + p0.x, a.y + bb[nf].y + p0.y);
            float2 o1 = make_float2(a.z + bb[nf].x + p1.x, a.w + bb[nf].y + p1.y);
            *(float2*)(or0 + nf * 8) = o0;
            *(float2*)(or1 + nf * 8) = o1;
        }
    }
}

// ---------------------------------------------------------------- launch
extern "C" void kernel_launch(void* const* d_in, const int* in_sizes, int n_in,
                              void* d_out, int out_size) {
    const float* video = (const float*)d_in[0];   // [64,16,1,84,84]
    const float* W     = (const float*)d_in[1];   // [1024,98]
    const float* bias  = (const float*)d_in[2];   // [1024]
    const float* pos   = (const float*)d_in[3];   // [1,1152,1024]
    float* out         = (float*)d_out;           // [64,1152,1024]

    cudaFuncSetAttribute(gemm_kernel, cudaFuncAttributeMaxDynamicSharedMemorySize,
                         SMEM_BYTES);

    gather_kernel<<<B_ * T_, 256>>>(video);
    wt_kernel<<<dim3(E_ / 32, (K_ + 31) / 32), dim3(32, 32)>>>(W);
    gemm_kernel<<<dim3(E_ / ET, M_ / MT), 256, SMEM_BYTES>>>(bias, pos, out);
}

// round 6
// speedup vs baseline: 2.5120x; 1.3958x over previous
#include <cuda_runtime.h>
#include <cuda_fp16.h>
#include <cstdint>

// ---------------------------------------------------------------- constants
#define B_     64
#define T_     16
#define IMG_   84
#define P_     7
#define NS_    144
#define K_     98
#define KP_    128          // K padded to 8 k16-steps (pad halves stay zero)
#define E_     1024
#define NTOK_  1152
#define M_     73728

// Scratch (device globals, zero-init; k in [98,128) never written -> zero pad)
__device__ __half g_A[(size_t)M_ * KP_];   // [m][k]  18.9 MB
__device__ __half g_B[(size_t)E_ * KP_];   // [e][k]  256 KB

// ---------------------------------------------------------------- helpers
__device__ __forceinline__ void mma_f16(float4& d, const uint32_t a[4],
                                        const uint32_t b[2]) {
    asm("mma.sync.aligned.m16n8k16.row.col.f32.f16.f16.f32 "
        "{%0,%1,%2,%3}, {%4,%5,%6,%7}, {%8,%9}, {%0,%1,%2,%3};"
        : "+f"(d.x), "+f"(d.y), "+f"(d.z), "+f"(d.w)
        : "r"(a[0]), "r"(a[1]), "r"(a[2]), "r"(a[3]), "r"(b[0]), "r"(b[1]));
}
__device__ __forceinline__ uint32_t smem_u32(const void* p) {
    uint32_t a;
    asm("{ .reg .u64 t; cvta.to.shared.u64 t, %1; cvt.u32.u64 %0, t; }"
        : "=r"(a) : "l"(p));
    return a;
}
__device__ __forceinline__ void cpasync16(uint32_t dst, const void* src) {
    asm volatile("cp.async.cg.shared.global [%0], [%1], 16;"
                 :: "r"(dst), "l"(src));
}
#define CP_COMMIT() asm volatile("cp.async.commit_group;" ::: "memory")
#define CP_WAIT(n)  asm volatile("cp.async.wait_group %0;" :: "n"(n) : "memory")

// ---------------------------------------------------------------- prep
__global__ void gather_kernel(const float* __restrict__ video) {
    __shared__ float frame[IMG_ * IMG_];
    int bt = blockIdx.x, b = bt >> 4, t = bt & 15;
    const float* src = video + (size_t)bt * (IMG_ * IMG_);
    for (int i = threadIdx.x; i < IMG_ * IMG_; i += blockDim.x) frame[i] = src[i];
    __syncthreads();

    int d = t >> 1, ts = t & 1;
    int mbase = b * NTOK_ + d * NS_;
    // s-major indexing: adjacent threads -> adjacent k -> contiguous 2B writes
    for (int i = threadIdx.x; i < NS_ * 49; i += blockDim.x) {
        int s = i / 49, k = i - s * 49;
        int pi = k / P_, pj = k - pi * P_;
        int h = s / 12, w = s - h * 12;
        float v = frame[(h * P_ + pi) * IMG_ + (w * P_ + pj)];
        g_A[(size_t)(mbase + s) * KP_ + ts * 49 + k] = __float2half_rn(v);
    }
}

__global__ void wk_kernel(const float* __restrict__ W) {
    int idx = blockIdx.x * blockDim.x + threadIdx.x;
    if (idx >= E_ * K_) return;
    int e = idx / K_, k = idx - e * K_;
    g_B[(size_t)e * KP_ + k] = __float2half_rn(W[idx]);
}

// ---------------------------------------------------------------- GEMM
// CTA tile 256(m) x 128(e); 8 warps, each 64x64. fp16 m16n8k16.
// K split in 2 chunks of 64 halves, cp.async double-buffered.
#define MT   256
#define ET   128
#define KC   64             // halves per chunk
#define SAW  72             // smem row stride (halves): 36 words, conflict-free
#define SAB  (256 * SAW)    // halves per A buffer
#define SBB  (128 * SAW)
#define SMEM_BYTES ((2 * SAB + 2 * SBB) * 2)   // 110592 B

__global__ __launch_bounds__(256, 1)
void gemm_kernel(const float* __restrict__ bias,
                 const float* __restrict__ pos,
                 float* __restrict__ out) {
    extern __shared__ __half sm[];
    __half* sA = sm;                  // [2][256][SAW]
    __half* sB = sm + 2 * SAB;        // [2][128][SAW]
    const uint32_t sA_u = smem_u32(sA);
    const uint32_t sB_u = smem_u32(sB);

    const int tid  = threadIdx.x;
    const int lane = tid & 31;
    const int wid  = tid >> 5;
    const int grp  = lane >> 2;        // 0..7
    const int tg   = lane & 3;         // 0..3
    const int wm   = wid & 3;          // m-quadrant -> wm*64
    const int wn   = wid >> 2;         // e-half     -> wn*64

    const int e0 = blockIdx.x * ET;
    const int m0 = blockIdx.y * MT;

    const int rr = tid >> 3;           // 0..31 row within pass
    const int ch = tid & 7;            // 16B chunk within 128B row-chunk

    const __half* gA = g_A + (size_t)m0 * KP_;
    const __half* gB = g_B + (size_t)e0 * KP_;

    auto stage = [&](int c, int buf) {
        const __half* a = gA + c * KC + ch * 8;
        uint32_t dA = sA_u + (uint32_t)(buf * SAB) * 2 + ch * 16;
#pragma unroll
        for (int p = 0; p < 8; ++p) {
            int row = p * 32 + rr;
            cpasync16(dA + row * (SAW * 2), a + (size_t)row * KP_);
        }
        const __half* b = gB + c * KC + ch * 8;
        uint32_t dB = sB_u + (uint32_t)(buf * SBB) * 2 + ch * 16;
#pragma unroll
        for (int p = 0; p < 4; ++p) {
            int row = p * 32 + rr;
            cpasync16(dB + row * (SAW * 2), b + (size_t)row * KP_);
        }
        CP_COMMIT();
    };

    float4 acc[4][8];
#pragma unroll
    for (int i = 0; i < 4; ++i)
#pragma unroll
        for (int j = 0; j < 8; ++j) acc[i][j] = make_float4(0.f, 0.f, 0.f, 0.f);

    stage(0, 0);
    stage(1, 1);

#pragma unroll
    for (int c = 0; c < 2; ++c) {
        if (c == 0) { CP_WAIT(1); } else { CP_WAIT(0); }
        __syncthreads();
        const __half* bA = sA + c * SAB;
        const __half* bB = sB + c * SBB;

#pragma unroll
        for (int ks = 0; ks < 4; ++ks) {
            const int ko = ks * 16 + tg * 2;
            uint32_t af[4][4], bf[8][2];
#pragma unroll
            for (int mf = 0; mf < 4; ++mf) {
                const __half* r0 = bA + (wm * 64 + mf * 16 + grp) * SAW + ko;
                af[mf][0] = *(const uint32_t*)r0;
                af[mf][1] = *(const uint32_t*)(r0 + 8 * SAW);
                af[mf][2] = *(const uint32_t*)(r0 + 8);
                af[mf][3] = *(const uint32_t*)(r0 + 8 * SAW + 8);
            }
#pragma unroll
            for (int nf = 0; nf < 8; ++nf) {
                const __half* r0 = bB + (wn * 64 + nf * 8 + grp) * SAW + ko;
                bf[nf][0] = *(const uint32_t*)r0;
                bf[nf][1] = *(const uint32_t*)(r0 + 8);
            }
#pragma unroll
            for (int mf = 0; mf < 4; ++mf)
#pragma unroll
                for (int nf = 0; nf < 8; ++nf)
                    mma_f16(acc[mf][nf], af[mf], bf[nf]);
        }
        __syncthreads();
    }

    // ---- epilogue: out = acc + bias + pos, streaming stores ----
    const int n0 = m0 % NTOK_;
    float2 bb[8];
#pragma unroll
    for (int nf = 0; nf < 8; ++nf)
        bb[nf] = *(const float2*)(bias + e0 + wn * 64 + nf * 8 + tg * 2);

#pragma unroll
    for (int mf = 0; mf < 4; ++mf) {
        int rl = wm * 64 + mf * 16 + grp;
        int m  = m0 + rl;
        int n  = n0 + rl;        if (n  >= NTOK_) n  -= NTOK_;
        int n2 = n0 + rl + 8;    if (n2 >= NTOK_) n2 -= NTOK_;
        const float* pr0 = pos + (size_t)n  * E_ + e0 + wn * 64 + tg * 2;
        const float* pr1 = pos + (size_t)n2 * E_ + e0 + wn * 64 + tg * 2;
        float* or0 = out + (size_t)m * E_ + e0 + wn * 64 + tg * 2;
        float* or1 = or0 + 8 * E_;
#pragma unroll
        for (int nf = 0; nf < 8; ++nf) {
            float2 p0 = *(const float2*)(pr0 + nf * 8);
            float2 p1 = *(const float2*)(pr1 + nf * 8);
            float4 a  = acc[mf][nf];
            float2 o0 = make_float2(a.x + bb[nf].x + p0.x, a.y + bb[nf].y + p0.y);
            float2 o1 = make_float2(a.z + bb[nf].x + p1.x, a.w + bb[nf].y + p1.y);
            __stcs((float2*)(or0 + nf * 8), o0);
            __stcs((float2*)(or1 + nf * 8), o1);
        }
    }
}

// ---------------------------------------------------------------- launch
extern "C" void kernel_launch(void* const* d_in, const int* in_sizes, int n_in,
                              void* d_out, int out_size) {
    const float* video = (const float*)d_in[0];   // [64,16,1,84,84]
    const float* W     = (const float*)d_in[1];   // [1024,98]
    const float* bias  = (const float*)d_in[2];   // [1024]
    const float* pos   = (const float*)d_in[3];   // [1,1152,1024]
    float* out         = (float*)d_out;           // [64,1152,1024]

    cudaFuncSetAttribute(gemm_kernel, cudaFuncAttributeMaxDynamicSharedMemorySize,
                         SMEM_BYTES);

    gather_kernel<<<B_ * T_, 256>>>(video);
    wk_kernel<<<(E_ * K_ + 255) / 256, 256>>>(W);
    gemm_kernel<<<dim3(E_ / ET, M_ / MT), 256, SMEM_BYTES>>>(bias, pos, out);
}